// round 11
// baseline (speedup 1.0000x reference)
#include <cuda_runtime.h>
#include <math.h>
#include <stdint.h>

// ConvolutionalCapsule EM routing, R8: 1024 threads/CTA, register votes
// (16 octants x 9 input capsules, 36 vote regs/thread, 64-reg cap = full RF,
// 32 warps/SM). Dedicated 256-thread stats phase stages packed A/B/C.
// One CTA per output position (1152 CTAs).
// Thread t = h*64 + om*4 + pq owns votes[i=h*9..+8][om][pose row pq] in regs.

#define EPS 1e-9f
#define LOG2E 1.4426950408889634f
#define NPOS 1152
#define ICAP 144

// smem float offsets
#define OFF_RR   0        // [144][16] rr (softmax output)
#define OFF_ACTS 2304     // [144] (+pad)
#define OFF_PC1  2464     // S1: [16][64] float4 (4096 floats)
#define OFF_PC2  6560     // S2: [16][64] float4 (4096 floats)
#define OFF_PC0  10656    // S0: [16][64]        (1024 floats)
#define OFF_EP   11680    // [144][68] E-step cells (stride 17 float4)
#define OFF_A    21472    // [256] av   (packed: [t63][c])
#define OFF_B    21728    // [256] bco
#define OFF_C    21984    // [16]
#define SMEM_FLOATS 22000
#define SMEM_BYTES (SMEM_FLOATS * 4)

typedef unsigned long long ull;

__device__ __forceinline__ ull pk2(float lo, float hi) {
    ull d;
    asm("mov.b64 %0, {%1, %2};" : "=l"(d)
        : "r"(__float_as_uint(lo)), "r"(__float_as_uint(hi)));
    return d;
}
__device__ __forceinline__ void upk2(ull v, float& lo, float& hi) {
    unsigned a, b;
    asm("mov.b64 {%0, %1}, %2;" : "=r"(a), "=r"(b) : "l"(v));
    lo = __uint_as_float(a); hi = __uint_as_float(b);
}
__device__ __forceinline__ ull fma2(ull a, ull b, ull c) {
    ull d; asm("fma.rn.f32x2 %0, %1, %2, %3;" : "=l"(d) : "l"(a), "l"(b), "l"(c));
    return d;
}
__device__ __forceinline__ ull mul2(ull a, ull b) {
    ull d; asm("mul.rn.f32x2 %0, %1, %2;" : "=l"(d) : "l"(a), "l"(b));
    return d;
}
__device__ __forceinline__ ull add2(ull a, ull b) {
    ull d; asm("add.rn.f32x2 %0, %1, %2;" : "=l"(d) : "l"(a), "l"(b));
    return d;
}

__global__ __launch_bounds__(1024, 1)
void caps_em_kernel(const float* __restrict__ pose_in,   // [8,14,14,256]
                    const float* __restrict__ act_in,    // [8,14,14,16]
                    const float* __restrict__ w,         // [144,16,4,4]
                    const float* __restrict__ beta_v,    // [16]
                    const float* __restrict__ beta_a,    // [16]
                    float* __restrict__ out)             // pose[1152,256] ++ act[1152,16]
{
    extern __shared__ float sm[];
    float* rr   = sm + OFF_RR;
    float* acts = sm + OFF_ACTS;
    float* pc1  = sm + OFF_PC1;
    float* pc2  = sm + OFF_PC2;
    float* pc0  = sm + OFF_PC0;
    float* ep   = sm + OFF_EP;
    float* a_sm = sm + OFF_A;
    float* b_sm = sm + OFF_B;
    float* c_sm = sm + OFF_C;

    const int n = blockIdx.x;
    const int x = n % 12;
    const int y = (n / 12) % 12;
    const int b = n / 144;
    const int t = threadIdx.x;

    const int h   = t >> 6;         // 0..15 (I-16th: i = h*9 + j)
    const int t63 = t & 63;         // om*4 + pq
    const int om  = (t >> 2) & 15;  // output capsule
    const int pq  = t & 3;          // pose row quad
    const int i0  = h * 9;
    // stats mapping (t < 256)
    const int os = t >> 4;
    const int ps = t & 15;

    // ---- stage acts ----
    if (t < ICAP) {
        const int kp = t >> 4;
        const int base = (b * 14 + (y + kp / 3)) * 14 + (x + kp % 3);
        acts[t] = act_in[base * 16 + (t & 15)];
    }

    // ---- build votes directly from gmem into registers ----
    ull va[9], vb[9];
    #pragma unroll
    for (int j = 0; j < 9; ++j) {
        const int i  = i0 + j;
        const int kp = i >> 4, ic = i & 15;
        const int base = (b * 14 + (y + kp / 3)) * 14 + (x + kp % 3);
        const float4 pr = *(const float4*)(pose_in + (size_t)base * 256 + ic * 16 + pq * 4);
        const ulonglong2* wp = (const ulonglong2*)(w + ((size_t)i * 16 + om) * 16);
        const ulonglong2 w0 = wp[0], w1 = wp[1], w2 = wp[2], w3 = wp[3];
        const ull a0 = pk2(pr.x, pr.x), a1 = pk2(pr.y, pr.y);
        const ull a2 = pk2(pr.z, pr.z), a3 = pk2(pr.w, pr.w);
        ull s01 = mul2(a0, w0.x);
        ull s23 = mul2(a0, w0.y);
        s01 = fma2(a1, w1.x, s01);  s23 = fma2(a1, w1.y, s23);
        s01 = fma2(a2, w2.x, s01);  s23 = fma2(a2, w2.y, s23);
        s01 = fma2(a3, w3.x, s01);  s23 = fma2(a3, w3.y, s23);
        va[j] = s01; vb[j] = s23;
    }
    __syncthreads();   // acts ready

    for (int it = 0; it < 3; ++it) {
        // ---- M-step partials from register votes (9 i's each) ----
        float S0 = 0.f;
        ull S1a = 0, S1b = 0, S2a = 0, S2b = 0;
        if (it == 0) {
            #pragma unroll
            for (int j = 0; j < 9; ++j) {
                const float rp = acts[i0 + j] * 0.0625f;
                const ull rp2 = pk2(rp, rp);
                const ull t01 = mul2(rp2, va[j]);
                const ull t23 = mul2(rp2, vb[j]);
                S0 += rp;
                S1a = add2(S1a, t01); S1b = add2(S1b, t23);
                S2a = fma2(t01, va[j], S2a); S2b = fma2(t23, vb[j], S2b);
            }
        } else {
            #pragma unroll
            for (int j = 0; j < 9; ++j) {
                const float rp = rr[(i0 + j) * 16 + om];   // already * acts (folded)
                const ull rp2 = pk2(rp, rp);
                const ull t01 = mul2(rp2, va[j]);
                const ull t23 = mul2(rp2, vb[j]);
                S0 += rp;
                S1a = add2(S1a, t01); S1b = add2(S1b, t23);
                S2a = fma2(t01, va[j], S2a); S2b = fma2(t23, vb[j], S2b);
            }
        }
        {
            ulonglong2 u;
            u.x = S1a; u.y = S1b; ((ulonglong2*)pc1)[h * 64 + t63] = u;
            u.x = S2a; u.y = S2b; ((ulonglong2*)pc2)[h * 64 + t63] = u;
            pc0[h * 64 + t63] = S0;
        }
        __syncthreads();

        // ---- stats phase: 256 threads, one (o,p) each, scalar coalesced ----
        if (t < 256) {
            // element index into pc float4 arrays: [g][c] with g=os*4+(ps>>2), c=ps&3
            const int fi = t;                // == g*4 + c (identity)
            const int gi = t >> 2;           // g
            float s0 = 0.f, s1 = 0.f, s2 = 0.f;
            #pragma unroll
            for (int hh = 0; hh < 16; ++hh) {
                s1 += pc1[hh * 256 + fi];
                s2 += pc2[hh * 256 + fi];
                s0 += pc0[hh * 64 + gi];
            }
            const float inv_rs = __fdividef(1.f, s0 + EPS);
            const float mean = s1 * inv_rs;
            float varsum = s2 - 2.f * mean * s1 + mean * mean * s0;
            varsum = fmaxf(varsum, 0.f);
            const float stdv = sqrtf(varsum * inv_rs);
            const float lg   = __logf(stdv + EPS);
            const float invd = __fdividef(1.f, 2.f * stdv * stdv + EPS);
            const float av   = invd * LOG2E;
            const float bco  = mean * av;

            float L = lg, MBs = mean * bco;
            #pragma unroll
            for (int d = 8; d; d >>= 1) {
                L   += __shfl_xor_sync(0xffffffffu, L,   d);
                MBs += __shfl_xor_sync(0xffffffffu, MBs, d);
            }

            const float costsum = (16.f * beta_v[os] + L) * s0;
            const float itemp = 1.f + (float)it;
            const float oact = __fdividef(1.f, 1.f + __expf(-(itemp * (beta_a[os] - costsum))));

            if (it == 2) {
                out[n * 256 + t] = mean;
                if (ps == 0) out[NPOS * 256 + n * 16 + os] = oact;
            } else {
                a_sm[t] = av;               // packed: [t63][c] by identity
                b_sm[t] = bco;
                if (ps == 0) c_sm[os] = (__logf(oact + EPS) - L) * LOG2E - MBs;
            }
        }
        if (it == 2) return;
        __syncthreads();

        // ---- E-step cells from register votes ----
        {
            const ull A01 = ((const ulonglong2*)a_sm)[t63].x;
            const ull A23 = ((const ulonglong2*)a_sm)[t63].y;
            const ulonglong2 Bv = ((const ulonglong2*)b_sm)[t63];
            const ull n2 = pk2(-2.f, -2.f);
            const ull B01 = mul2(Bv.x, n2);
            const ull B23 = mul2(Bv.y, n2);
            const float C4 = c_sm[om] * 0.25f;
            #pragma unroll
            for (int j = 0; j < 9; ++j) {
                const ull u01 = fma2(va[j], A01, B01);
                const ull u23 = fma2(vb[j], A23, B23);
                ull s = mul2(va[j], u01);
                s = fma2(vb[j], u23, s);
                float lo, hi; upk2(s, lo, hi);
                ep[(i0 + j) * 68 + t63] = C4 - (lo + hi);
            }
        }
        __syncthreads();

        // ---- paired-lane softmax: lanes (2i, 2i+1) split the 16 o's ----
        if (t < 2 * ICAP) {
            const int i = t >> 1, half = t & 1;
            const float4* eprow = (const float4*)(ep + i * 68);
            float z[8];
            float mx = -3.4e38f;
            #pragma unroll
            for (int k = 0; k < 8; ++k) {
                const int kk = (k + 4 * half) & 7;        // bank stagger between halves
                const float4 P = eprow[half * 8 + kk];
                const float zz = (P.x + P.y) + (P.z + P.w);
                z[kk] = zz;
                mx = fmaxf(mx, zz);
            }
            mx = fmaxf(mx, __shfl_xor_sync(0xffffffffu, mx, 1));
            float ss = 0.f;
            #pragma unroll
            for (int k = 0; k < 8; ++k) {
                z[k] = exp2f(z[k] - mx);
                ss += z[k];
            }
            ss += __shfl_xor_sync(0xffffffffu, ss, 1);
            const float scale = acts[i] * __fdividef(1.f, ss);   // fold acts into rr
            float4 r0, r1;
            r0.x = z[0] * scale; r0.y = z[1] * scale; r0.z = z[2] * scale; r0.w = z[3] * scale;
            r1.x = z[4] * scale; r1.y = z[5] * scale; r1.z = z[6] * scale; r1.w = z[7] * scale;
            float4* dst = (float4*)(rr + i * 16 + half * 8);
            dst[0] = r0; dst[1] = r1;
        }
        __syncthreads();
    }
}

extern "C" void kernel_launch(void* const* d_in, const int* in_sizes, int n_in,
                              void* d_out, int out_size) {
    const float* pose_in = (const float*)d_in[0];
    const float* act_in  = (const float*)d_in[1];
    const float* w       = (const float*)d_in[2];
    const float* beta_v  = (const float*)d_in[3];
    const float* beta_a  = (const float*)d_in[4];
    float* out = (float*)d_out;

    cudaFuncSetAttribute(caps_em_kernel,
                         cudaFuncAttributeMaxDynamicSharedMemorySize, SMEM_BYTES);
    caps_em_kernel<<<NPOS, 1024, SMEM_BYTES>>>(pose_in, act_in, w, beta_v, beta_a, out);
}

// round 12
// speedup vs baseline: 1.1433x; 1.1433x over previous
#include <cuda_runtime.h>
#include <math.h>
#include <stdint.h>

// ConvolutionalCapsule EM routing, R9: 512 threads/CTA, register votes with
// 2-row ownership: t = h*32 + om*2 + pd (h in 0..15, 9 i's each; pd = row-pair).
// Thread owns votes[i=h*9..+8][om][rows 2pd,2pd+1] in regs (72 floats).
// w LDGs amortized over 2 rows (54 LDG/thread vs 90), loops 9-deep not 18.
// One CTA per output position (1152 CTAs).

#define EPS 1e-9f
#define LOG2E 1.4426950408889634f
#define NPOS 1152
#define ICAP 144

// smem float offsets
#define OFF_RR    0        // [144][16] rr (softmax output)
#define OFF_ACTS  2304     // [144] (+pad)
#define OFF_BASE  2464     // [16] int row-base table (9 used)
#define OFF_PC1   2480     // S1: [16][256]  (h, om*16+p)
#define OFF_PC2   6576     // S2: [16][256]
#define OFF_PC0   10672    // S0: [16][32]   (h, om*2+pd)
#define OFF_EP    11184    // [144][36] E-step cells (om*2+pd, padded)
#define OFF_A     16368    // [256] av  (o*16+p)
#define OFF_B     16624    // [256] bco
#define OFF_C     16880    // [16]
#define SMEM_FLOATS 16896
#define SMEM_BYTES (SMEM_FLOATS * 4)

typedef unsigned long long ull;

__device__ __forceinline__ ull pk2(float lo, float hi) {
    ull d;
    asm("mov.b64 %0, {%1, %2};" : "=l"(d)
        : "r"(__float_as_uint(lo)), "r"(__float_as_uint(hi)));
    return d;
}
__device__ __forceinline__ void upk2(ull v, float& lo, float& hi) {
    unsigned a, b;
    asm("mov.b64 {%0, %1}, %2;" : "=r"(a), "=r"(b) : "l"(v));
    lo = __uint_as_float(a); hi = __uint_as_float(b);
}
__device__ __forceinline__ ull fma2(ull a, ull b, ull c) {
    ull d; asm("fma.rn.f32x2 %0, %1, %2, %3;" : "=l"(d) : "l"(a), "l"(b), "l"(c));
    return d;
}
__device__ __forceinline__ ull mul2(ull a, ull b) {
    ull d; asm("mul.rn.f32x2 %0, %1, %2;" : "=l"(d) : "l"(a), "l"(b));
    return d;
}
__device__ __forceinline__ ull add2(ull a, ull b) {
    ull d; asm("add.rn.f32x2 %0, %1, %2;" : "=l"(d) : "l"(a), "l"(b));
    return d;
}

__global__ __launch_bounds__(512, 1)
void caps_em_kernel(const float* __restrict__ pose_in,   // [8,14,14,256]
                    const float* __restrict__ act_in,    // [8,14,14,16]
                    const float* __restrict__ w,         // [144,16,4,4]
                    const float* __restrict__ beta_v,    // [16]
                    const float* __restrict__ beta_a,    // [16]
                    float* __restrict__ out)             // pose[1152,256] ++ act[1152,16]
{
    extern __shared__ float sm[];
    float* rr    = sm + OFF_RR;
    float* acts  = sm + OFF_ACTS;
    int*   baseK = (int*)(sm + OFF_BASE);
    float* pc1   = sm + OFF_PC1;
    float* pc2   = sm + OFF_PC2;
    float* pc0   = sm + OFF_PC0;
    float* ep    = sm + OFF_EP;
    float* a_sm  = sm + OFF_A;
    float* b_sm  = sm + OFF_B;
    float* c_sm  = sm + OFF_C;

    const int n = blockIdx.x;
    const int x = n % 12;
    const int y = (n / 12) % 12;
    const int b = n / 144;
    const int t = threadIdx.x;

    const int h  = t >> 5;          // 0..15: i = h*9 + j
    const int om = (t >> 1) & 15;   // output capsule
    const int pd = t & 1;           // row pair: rows 2pd, 2pd+1
    const int i0 = h * 9;
    // stats mapping (t < 256)
    const int os = t >> 4;
    const int ps = t & 15;

    // ---- row-base table (9 kernel positions) ----
    if (t < 9)
        baseK[t] = (b * 14 + (y + t / 3)) * 14 + (x + t % 3);
    __syncthreads();

    // ---- stage acts ----
    if (t < ICAP)
        acts[t] = act_in[baseK[t >> 4] * 16 + (t & 15)];

    // ---- build votes into registers (rows 2pd, 2pd+1 of each i) ----
    ull vA0[9], vA1[9], vB0[9], vB1[9];
    #pragma unroll
    for (int j = 0; j < 9; ++j) {
        const int i = i0 + j;
        const float* pp = pose_in + (size_t)baseK[i >> 4] * 256 + (i & 15) * 16 + pd * 8;
        const float4 pr0 = *(const float4*)pp;
        const float4 pr1 = *(const float4*)(pp + 4);
        const ulonglong2* wp = (const ulonglong2*)(w + ((size_t)i * 16 + om) * 16);
        const ulonglong2 w0 = wp[0], w1 = wp[1], w2 = wp[2], w3 = wp[3];
        // row A = pr0 @ w
        {
            const ull a0 = pk2(pr0.x, pr0.x), a1 = pk2(pr0.y, pr0.y);
            const ull a2 = pk2(pr0.z, pr0.z), a3 = pk2(pr0.w, pr0.w);
            ull s01 = mul2(a0, w0.x), s23 = mul2(a0, w0.y);
            s01 = fma2(a1, w1.x, s01);  s23 = fma2(a1, w1.y, s23);
            s01 = fma2(a2, w2.x, s01);  s23 = fma2(a2, w2.y, s23);
            s01 = fma2(a3, w3.x, s01);  s23 = fma2(a3, w3.y, s23);
            vA0[j] = s01; vA1[j] = s23;
        }
        // row B = pr1 @ w
        {
            const ull a0 = pk2(pr1.x, pr1.x), a1 = pk2(pr1.y, pr1.y);
            const ull a2 = pk2(pr1.z, pr1.z), a3 = pk2(pr1.w, pr1.w);
            ull s01 = mul2(a0, w0.x), s23 = mul2(a0, w0.y);
            s01 = fma2(a1, w1.x, s01);  s23 = fma2(a1, w1.y, s23);
            s01 = fma2(a2, w2.x, s01);  s23 = fma2(a2, w2.y, s23);
            s01 = fma2(a3, w3.x, s01);  s23 = fma2(a3, w3.y, s23);
            vB0[j] = s01; vB1[j] = s23;
        }
    }
    __syncthreads();   // acts ready

    for (int it = 0; it < 3; ++it) {
        // ---- M-step partials from register votes (9 i's, 8 values each) ----
        float S0 = 0.f;
        ull S1A0 = 0, S1A1 = 0, S1B0 = 0, S1B1 = 0;
        ull S2A0 = 0, S2A1 = 0, S2B0 = 0, S2B1 = 0;
        if (it == 0) {
            #pragma unroll
            for (int j = 0; j < 9; ++j) {
                const float rp = acts[i0 + j] * 0.0625f;
                const ull rp2 = pk2(rp, rp);
                S0 += rp;
                ull u;
                u = mul2(rp2, vA0[j]); S1A0 = add2(S1A0, u); S2A0 = fma2(u, vA0[j], S2A0);
                u = mul2(rp2, vA1[j]); S1A1 = add2(S1A1, u); S2A1 = fma2(u, vA1[j], S2A1);
                u = mul2(rp2, vB0[j]); S1B0 = add2(S1B0, u); S2B0 = fma2(u, vB0[j], S2B0);
                u = mul2(rp2, vB1[j]); S1B1 = add2(S1B1, u); S2B1 = fma2(u, vB1[j], S2B1);
            }
        } else {
            #pragma unroll
            for (int j = 0; j < 9; ++j) {
                const float rp = rr[(i0 + j) * 16 + om];   // already * acts (folded)
                const ull rp2 = pk2(rp, rp);
                S0 += rp;
                ull u;
                u = mul2(rp2, vA0[j]); S1A0 = add2(S1A0, u); S2A0 = fma2(u, vA0[j], S2A0);
                u = mul2(rp2, vA1[j]); S1A1 = add2(S1A1, u); S2A1 = fma2(u, vA1[j], S2A1);
                u = mul2(rp2, vB0[j]); S1B0 = add2(S1B0, u); S2B0 = fma2(u, vB0[j], S2B0);
                u = mul2(rp2, vB1[j]); S1B1 = add2(S1B1, u); S2B1 = fma2(u, vB1[j], S2B1);
            }
        }
        {
            // natural layout: pc1[h*256 + om*16 + p], p = pd*8 + r*4 + c
            const int f4 = h * 64 + om * 4 + pd * 2;   // float4 index
            ulonglong2 u;
            u.x = S1A0; u.y = S1A1; ((ulonglong2*)pc1)[f4]     = u;
            u.x = S1B0; u.y = S1B1; ((ulonglong2*)pc1)[f4 + 1] = u;
            u.x = S2A0; u.y = S2A1; ((ulonglong2*)pc2)[f4]     = u;
            u.x = S2B0; u.y = S2B1; ((ulonglong2*)pc2)[f4 + 1] = u;
            pc0[h * 32 + om * 2 + pd] = S0;
        }
        __syncthreads();

        // ---- stats phase: 256 threads, one (o,p) each, coalesced gather ----
        if (t < 256) {
            const int s0i = os * 2 + (ps >> 3);
            float s0 = 0.f, s1 = 0.f, s2 = 0.f;
            #pragma unroll
            for (int hh = 0; hh < 16; ++hh) {
                s1 += pc1[hh * 256 + t];
                s2 += pc2[hh * 256 + t];
                s0 += pc0[hh * 32 + s0i];
            }
            const float inv_rs = __fdividef(1.f, s0 + EPS);
            const float mean = s1 * inv_rs;
            float varsum = s2 - 2.f * mean * s1 + mean * mean * s0;
            varsum = fmaxf(varsum, 0.f);
            const float stdv = sqrtf(varsum * inv_rs);
            const float lg   = __logf(stdv + EPS);
            const float invd = __fdividef(1.f, 2.f * stdv * stdv + EPS);
            const float av   = invd * LOG2E;
            const float bco  = mean * av;

            float L = lg, MBs = mean * bco;
            #pragma unroll
            for (int d = 8; d; d >>= 1) {
                L   += __shfl_xor_sync(0xffffffffu, L,   d);
                MBs += __shfl_xor_sync(0xffffffffu, MBs, d);
            }

            const float costsum = (16.f * beta_v[os] + L) * s0;
            const float itemp = 1.f + (float)it;
            const float oact = __fdividef(1.f, 1.f + __expf(-(itemp * (beta_a[os] - costsum))));

            if (it == 2) {
                out[n * 256 + t] = mean;
                if (ps == 0) out[NPOS * 256 + n * 16 + os] = oact;
            } else {
                a_sm[t] = av;
                b_sm[t] = bco;
                if (ps == 0) c_sm[os] = (__logf(oact + EPS) - L) * LOG2E - MBs;
            }
        }
        if (it == 2) return;
        __syncthreads();

        // ---- E-step cells from register votes ----
        {
            const int f4 = om * 4 + pd * 2;
            const ulonglong2 Ar0 = ((const ulonglong2*)a_sm)[f4];      // row 2pd
            const ulonglong2 Ar1 = ((const ulonglong2*)a_sm)[f4 + 1];  // row 2pd+1
            ulonglong2 Br0 = ((const ulonglong2*)b_sm)[f4];
            ulonglong2 Br1 = ((const ulonglong2*)b_sm)[f4 + 1];
            const ull n2 = pk2(-2.f, -2.f);
            const ull BA0 = mul2(Br0.x, n2), BA1 = mul2(Br0.y, n2);
            const ull BB0 = mul2(Br1.x, n2), BB1 = mul2(Br1.y, n2);
            const float C2 = c_sm[om] * 0.5f;
            #pragma unroll
            for (int j = 0; j < 9; ++j) {
                ull s = mul2(vA0[j], fma2(vA0[j], Ar0.x, BA0));
                s = fma2(vA1[j], fma2(vA1[j], Ar0.y, BA1), s);
                s = fma2(vB0[j], fma2(vB0[j], Ar1.x, BB0), s);
                s = fma2(vB1[j], fma2(vB1[j], Ar1.y, BB1), s);
                float lo, hi; upk2(s, lo, hi);
                ep[(i0 + j) * 36 + om * 2 + pd] = C2 - (lo + hi);
            }
        }
        __syncthreads();

        // ---- paired-lane softmax: lanes (2i, 2i+1) split the 16 o's ----
        if (t < 2 * ICAP) {
            const int i = t >> 1, half = t & 1;
            const float4* eprow = (const float4*)(ep + i * 36) + half * 4;
            float z[8];
            float mx = -3.4e38f;
            #pragma unroll
            for (int k = 0; k < 4; ++k) {
                const int kk = (k + 2 * half) & 3;        // bank stagger between halves
                const float4 P = eprow[kk];               // cells (2o,2o+1) pairs
                const float z0 = P.x + P.y;
                const float z1 = P.z + P.w;
                z[kk * 2] = z0; z[kk * 2 + 1] = z1;
                mx = fmaxf(mx, fmaxf(z0, z1));
            }
            mx = fmaxf(mx, __shfl_xor_sync(0xffffffffu, mx, 1));
            float ss = 0.f;
            #pragma unroll
            for (int k = 0; k < 8; ++k) {
                z[k] = exp2f(z[k] - mx);
                ss += z[k];
            }
            ss += __shfl_xor_sync(0xffffffffu, ss, 1);
            const float scale = acts[i] * __fdividef(1.f, ss);   // fold acts into rr
            float4 r0, r1;
            r0.x = z[0] * scale; r0.y = z[1] * scale; r0.z = z[2] * scale; r0.w = z[3] * scale;
            r1.x = z[4] * scale; r1.y = z[5] * scale; r1.z = z[6] * scale; r1.w = z[7] * scale;
            float4* dst = (float4*)(rr + i * 16 + half * 8);
            dst[0] = r0; dst[1] = r1;
        }
        __syncthreads();
    }
}

extern "C" void kernel_launch(void* const* d_in, const int* in_sizes, int n_in,
                              void* d_out, int out_size) {
    const float* pose_in = (const float*)d_in[0];
    const float* act_in  = (const float*)d_in[1];
    const float* w       = (const float*)d_in[2];
    const float* beta_v  = (const float*)d_in[3];
    const float* beta_a  = (const float*)d_in[4];
    float* out = (float*)d_out;

    cudaFuncSetAttribute(caps_em_kernel,
                         cudaFuncAttributeMaxDynamicSharedMemorySize, SMEM_BYTES);
    caps_em_kernel<<<NPOS, 512, SMEM_BYTES>>>(pose_in, act_in, w, beta_v, beta_a, out);
}

// round 14
// speedup vs baseline: 1.2418x; 1.0862x over previous
#include <cuda_runtime.h>
#include <math.h>
#include <stdint.h>

// ConvolutionalCapsule EM routing, R10: R9 + pre-transposed w for coalesced
// vote-build loads + sqrt-free stats chain.
// Pre-kernel writes wT[i][r][om] (float4 granularity) so the build's four
// w LDG.128s per (i,warp) touch 256B contiguous each (2 L1 lines, not 8).
// Main kernel: 512 threads/CTA, t = h*32 + om*2 + pd; thread owns
// votes[i=h*9..+8][om][rows 2pd,2pd+1] in registers.

#define EPS 1e-9f
#define LOG2E 1.4426950408889634f
#define NPOS 1152
#define ICAP 144

// smem float offsets
#define OFF_RR    0        // [144][16] rr (softmax output)
#define OFF_ACTS  2304     // [144] (+pad)
#define OFF_BASE  2464     // [16] int row-base table (9 used)
#define OFF_PC1   2480     // S1: [16][256]  (h, om*16+p)
#define OFF_PC2   6576     // S2: [16][256]
#define OFF_PC0   10672    // S0: [16][32]   (h, om*2+pd)
#define OFF_EP    11184    // [144][36] E-step cells (om*2+pd, padded)
#define OFF_A     16368    // [256] av  (o*16+p)
#define OFF_B     16624    // [256] bco
#define OFF_C     16880    // [16]
#define SMEM_FLOATS 16896
#define SMEM_BYTES (SMEM_FLOATS * 4)

typedef unsigned long long ull;

// transposed weights: wT[i][r][om] as float4 (ulonglong2) blocks
__device__ ulonglong2 g_wT[144 * 64];

__device__ __forceinline__ ull pk2(float lo, float hi) {
    ull d;
    asm("mov.b64 %0, {%1, %2};" : "=l"(d)
        : "r"(__float_as_uint(lo)), "r"(__float_as_uint(hi)));
    return d;
}
__device__ __forceinline__ void upk2(ull v, float& lo, float& hi) {
    unsigned a, b;
    asm("mov.b64 {%0, %1}, %2;" : "=r"(a), "=r"(b) : "l"(v));
    lo = __uint_as_float(a); hi = __uint_as_float(b);
}
__device__ __forceinline__ ull fma2(ull a, ull b, ull c) {
    ull d; asm("fma.rn.f32x2 %0, %1, %2, %3;" : "=l"(d) : "l"(a), "l"(b), "l"(c));
    return d;
}
__device__ __forceinline__ ull mul2(ull a, ull b) {
    ull d; asm("mul.rn.f32x2 %0, %1, %2;" : "=l"(d) : "l"(a), "l"(b));
    return d;
}
__device__ __forceinline__ ull add2(ull a, ull b) {
    ull d; asm("add.rn.f32x2 %0, %1, %2;" : "=l"(d) : "l"(a), "l"(b));
    return d;
}

__global__ void transpose_w_kernel(const float* __restrict__ w) {
    const int idx = blockIdx.x * 256 + threadIdx.x;   // 9216 float4s
    if (idx < 144 * 64) {
        const int i  = idx >> 6;
        const int rm = idx & 63;
        const int r  = rm >> 4;
        const int om = rm & 15;
        g_wT[idx] = ((const ulonglong2*)w)[i * 64 + om * 4 + r];
    }
}

__global__ __launch_bounds__(512, 1)
void caps_em_kernel(const float* __restrict__ pose_in,   // [8,14,14,256]
                    const float* __restrict__ act_in,    // [8,14,14,16]
                    const float* __restrict__ beta_v,    // [16]
                    const float* __restrict__ beta_a,    // [16]
                    float* __restrict__ out)             // pose[1152,256] ++ act[1152,16]
{
    extern __shared__ float sm[];
    float* rr    = sm + OFF_RR;
    float* acts  = sm + OFF_ACTS;
    int*   baseK = (int*)(sm + OFF_BASE);
    float* pc1   = sm + OFF_PC1;
    float* pc2   = sm + OFF_PC2;
    float* pc0   = sm + OFF_PC0;
    float* ep    = sm + OFF_EP;
    float* a_sm  = sm + OFF_A;
    float* b_sm  = sm + OFF_B;
    float* c_sm  = sm + OFF_C;

    const int n = blockIdx.x;
    const int x = n % 12;
    const int y = (n / 12) % 12;
    const int b = n / 144;
    const int t = threadIdx.x;

    const int h  = t >> 5;          // 0..15: i = h*9 + j
    const int om = (t >> 1) & 15;   // output capsule
    const int pd = t & 1;           // row pair: rows 2pd, 2pd+1
    const int i0 = h * 9;
    // stats mapping (t < 256)
    const int os = t >> 4;
    const int ps = t & 15;

    // ---- row-base table (9 kernel positions) ----
    if (t < 9)
        baseK[t] = (b * 14 + (y + t / 3)) * 14 + (x + t % 3);
    __syncthreads();

    // ---- stage acts ----
    if (t < ICAP)
        acts[t] = act_in[baseK[t >> 4] * 16 + (t & 15)];

    // ---- build votes into registers (rows 2pd, 2pd+1 of each i) ----
    // w loads from g_wT: addresses i*1024 + r*256 + om*16 -> 256B contiguous
    // per access across the warp (pd pairs broadcast): 2 L1 lines, not 8.
    ull vA0[9], vA1[9], vB0[9], vB1[9];
    #pragma unroll
    for (int j = 0; j < 9; ++j) {
        const int i = i0 + j;
        const float* pp = pose_in + (size_t)baseK[i >> 4] * 256 + (i & 15) * 16 + pd * 8;
        const float4 pr0 = *(const float4*)pp;
        const float4 pr1 = *(const float4*)(pp + 4);
        const ulonglong2* wt = g_wT + (size_t)i * 64 + om;
        const ulonglong2 w0 = wt[0], w1 = wt[16], w2 = wt[32], w3 = wt[48];
        // rows 2pd (pr0) and 2pd+1 (pr1)
        {
            const ull a0 = pk2(pr0.x, pr0.x), a1 = pk2(pr0.y, pr0.y);
            const ull a2 = pk2(pr0.z, pr0.z), a3 = pk2(pr0.w, pr0.w);
            ull s01 = mul2(a0, w0.x), s23 = mul2(a0, w0.y);
            s01 = fma2(a1, w1.x, s01);  s23 = fma2(a1, w1.y, s23);
            s01 = fma2(a2, w2.x, s01);  s23 = fma2(a2, w2.y, s23);
            s01 = fma2(a3, w3.x, s01);  s23 = fma2(a3, w3.y, s23);
            vA0[j] = s01; vA1[j] = s23;
        }
        {
            const ull a0 = pk2(pr1.x, pr1.x), a1 = pk2(pr1.y, pr1.y);
            const ull a2 = pk2(pr1.z, pr1.z), a3 = pk2(pr1.w, pr1.w);
            ull s01 = mul2(a0, w0.x), s23 = mul2(a0, w0.y);
            s01 = fma2(a1, w1.x, s01);  s23 = fma2(a1, w1.y, s23);
            s01 = fma2(a2, w2.x, s01);  s23 = fma2(a2, w2.y, s23);
            s01 = fma2(a3, w3.x, s01);  s23 = fma2(a3, w3.y, s23);
            vB0[j] = s01; vB1[j] = s23;
        }
    }
    __syncthreads();   // acts ready

    for (int it = 0; it < 3; ++it) {
        // ---- M-step partials from register votes (9 i's, 8 values each) ----
        float S0 = 0.f;
        ull S1A0 = 0, S1A1 = 0, S1B0 = 0, S1B1 = 0;
        ull S2A0 = 0, S2A1 = 0, S2B0 = 0, S2B1 = 0;
        if (it == 0) {
            #pragma unroll
            for (int j = 0; j < 9; ++j) {
                const float rp = acts[i0 + j] * 0.0625f;
                const ull rp2 = pk2(rp, rp);
                S0 += rp;
                ull u;
                u = mul2(rp2, vA0[j]); S1A0 = add2(S1A0, u); S2A0 = fma2(u, vA0[j], S2A0);
                u = mul2(rp2, vA1[j]); S1A1 = add2(S1A1, u); S2A1 = fma2(u, vA1[j], S2A1);
                u = mul2(rp2, vB0[j]); S1B0 = add2(S1B0, u); S2B0 = fma2(u, vB0[j], S2B0);
                u = mul2(rp2, vB1[j]); S1B1 = add2(S1B1, u); S2B1 = fma2(u, vB1[j], S2B1);
            }
        } else {
            #pragma unroll
            for (int j = 0; j < 9; ++j) {
                const float rp = rr[(i0 + j) * 16 + om];   // already * acts (folded)
                const ull rp2 = pk2(rp, rp);
                S0 += rp;
                ull u;
                u = mul2(rp2, vA0[j]); S1A0 = add2(S1A0, u); S2A0 = fma2(u, vA0[j], S2A0);
                u = mul2(rp2, vA1[j]); S1A1 = add2(S1A1, u); S2A1 = fma2(u, vA1[j], S2A1);
                u = mul2(rp2, vB0[j]); S1B0 = add2(S1B0, u); S2B0 = fma2(u, vB0[j], S2B0);
                u = mul2(rp2, vB1[j]); S1B1 = add2(S1B1, u); S2B1 = fma2(u, vB1[j], S2B1);
            }
        }
        {
            // natural layout: pc1[h*256 + om*16 + p], p = pd*8 + r*4 + c
            const int f4 = h * 64 + om * 4 + pd * 2;   // float4 index
            ulonglong2 u;
            u.x = S1A0; u.y = S1A1; ((ulonglong2*)pc1)[f4]     = u;
            u.x = S1B0; u.y = S1B1; ((ulonglong2*)pc1)[f4 + 1] = u;
            u.x = S2A0; u.y = S2A1; ((ulonglong2*)pc2)[f4]     = u;
            u.x = S2B0; u.y = S2B1; ((ulonglong2*)pc2)[f4 + 1] = u;
            pc0[h * 32 + om * 2 + pd] = S0;
        }
        __syncthreads();

        // ---- stats phase: 256 threads, one (o,p) each, sqrt-free chain ----
        if (t < 256) {
            const int s0i = os * 2 + (ps >> 3);
            float s0 = 0.f, s1 = 0.f, s2 = 0.f;
            #pragma unroll
            for (int hh = 0; hh < 16; ++hh) {
                s1 += pc1[hh * 256 + t];
                s2 += pc2[hh * 256 + t];
                s0 += pc0[hh * 32 + s0i];
            }
            const float inv_rs = __fdividef(1.f, s0 + EPS);
            const float mean = s1 * inv_rs;
            float varsum = s2 - 2.f * mean * s1 + mean * mean * s0;
            varsum = fmaxf(varsum, 0.f);
            const float var = fmaxf(varsum * inv_rs, 1e-18f);     // sigma^2
            const float lg   = 0.5f * __logf(var);                // = log(sigma+~eps)
            const float invd = __fdividef(1.f, 2.f * var + EPS);  // 1/(2 sigma^2 + eps)
            const float av   = invd * LOG2E;
            const float bco  = mean * av;

            float L = lg, MBs = mean * bco;
            #pragma unroll
            for (int d = 8; d; d >>= 1) {
                L   += __shfl_xor_sync(0xffffffffu, L,   d);
                MBs += __shfl_xor_sync(0xffffffffu, MBs, d);
            }

            const float costsum = (16.f * beta_v[os] + L) * s0;
            const float itemp = 1.f + (float)it;
            const float oact = __fdividef(1.f, 1.f + __expf(-(itemp * (beta_a[os] - costsum))));

            if (it == 2) {
                out[n * 256 + t] = mean;
                if (ps == 0) out[NPOS * 256 + n * 16 + os] = oact;
            } else {
                a_sm[t] = av;
                b_sm[t] = bco;
                if (ps == 0) c_sm[os] = (__logf(oact + EPS) - L) * LOG2E - MBs;
            }
        }
        if (it == 2) return;
        __syncthreads();

        // ---- E-step cells from register votes ----
        {
            const int f4 = om * 4 + pd * 2;
            const ulonglong2 Ar0 = ((const ulonglong2*)a_sm)[f4];      // row 2pd
            const ulonglong2 Ar1 = ((const ulonglong2*)a_sm)[f4 + 1];  // row 2pd+1
            ulonglong2 Br0 = ((const ulonglong2*)b_sm)[f4];
            ulonglong2 Br1 = ((const ulonglong2*)b_sm)[f4 + 1];
            const ull n2 = pk2(-2.f, -2.f);
            const ull BA0 = mul2(Br0.x, n2), BA1 = mul2(Br0.y, n2);
            const ull BB0 = mul2(Br1.x, n2), BB1 = mul2(Br1.y, n2);
            const float C2 = c_sm[om] * 0.5f;
            #pragma unroll
            for (int j = 0; j < 9; ++j) {
                ull s = mul2(vA0[j], fma2(vA0[j], Ar0.x, BA0));
                s = fma2(vA1[j], fma2(vA1[j], Ar0.y, BA1), s);
                s = fma2(vB0[j], fma2(vB0[j], Ar1.x, BB0), s);
                s = fma2(vB1[j], fma2(vB1[j], Ar1.y, BB1), s);
                float lo, hi; upk2(s, lo, hi);
                ep[(i0 + j) * 36 + om * 2 + pd] = C2 - (lo + hi);
            }
        }
        __syncthreads();

        // ---- paired-lane softmax: lanes (2i, 2i+1) split the 16 o's ----
        if (t < 2 * ICAP) {
            const int i = t >> 1, half = t & 1;
            const float4* eprow = (const float4*)(ep + i * 36) + half * 4;
            float z[8];
            float mx = -3.4e38f;
            #pragma unroll
            for (int k = 0; k < 4; ++k) {
                const int kk = (k + 2 * half) & 3;        // bank stagger between halves
                const float4 P = eprow[kk];               // cells (2o,2o+1) pairs
                const float z0 = P.x + P.y;
                const float z1 = P.z + P.w;
                z[kk * 2] = z0; z[kk * 2 + 1] = z1;
                mx = fmaxf(mx, fmaxf(z0, z1));
            }
            mx = fmaxf(mx, __shfl_xor_sync(0xffffffffu, mx, 1));
            float ss = 0.f;
            #pragma unroll
            for (int k = 0; k < 8; ++k) {
                z[k] = exp2f(z[k] - mx);
                ss += z[k];
            }
            ss += __shfl_xor_sync(0xffffffffu, ss, 1);
            const float scale = acts[i] * __fdividef(1.f, ss);   // fold acts into rr
            float4 r0, r1;
            r0.x = z[0] * scale; r0.y = z[1] * scale; r0.z = z[2] * scale; r0.w = z[3] * scale;
            r1.x = z[4] * scale; r1.y = z[5] * scale; r1.z = z[6] * scale; r1.w = z[7] * scale;
            float4* dst = (float4*)(rr + i * 16 + half * 8);
            dst[0] = r0; dst[1] = r1;
        }
        __syncthreads();
    }
}

extern "C" void kernel_launch(void* const* d_in, const int* in_sizes, int n_in,
                              void* d_out, int out_size) {
    const float* pose_in = (const float*)d_in[0];
    const float* act_in  = (const float*)d_in[1];
    const float* w       = (const float*)d_in[2];
    const float* beta_v  = (const float*)d_in[3];
    const float* beta_a  = (const float*)d_in[4];
    float* out = (float*)d_out;

    transpose_w_kernel<<<36, 256>>>(w);

    cudaFuncSetAttribute(caps_em_kernel,
                         cudaFuncAttributeMaxDynamicSharedMemorySize, SMEM_BYTES);
    caps_em_kernel<<<NPOS, 512, SMEM_BYTES>>>(pose_in, act_in, beta_v, beta_a, out);
}